// round 6
// baseline (speedup 1.0000x reference)
#include <cuda_runtime.h>

// Problem constants (fixed by the dataset)
#define NMAX 100000
#define EMAX 1600000

// ---------------- device scratch (no runtime allocation allowed) ------------
__device__ float4 g_bufA[NMAX * 128 / 4];   // 51.2 MB ping
__device__ float4 g_bufB[NMAX * 128 / 4];   // 51.2 MB pong
__device__ float  g_dinv[NMAX];
__device__ int    g_cnt[NMAX];
__device__ int    g_off[NMAX];
__device__ int    g_cursor[NMAX];
__device__ int    g_srt[EMAX];              // edge src sorted by dst (CSR)
__device__ float  g_wsr[EMAX];              // dinv[src] per sorted edge
__device__ int    g_bsum[128];
__device__ float  g_scale[4 * 128];         // folded BN scale per layer
__device__ float  g_shift[4 * 128];         // folded BN shift per layer

// ---------------- CSR build ------------------------------------------------
__global__ void zero_cnt_k(int N) {
    int i = blockIdx.x * blockDim.x + threadIdx.x;
    if (i < N) g_cnt[i] = 0;
}

__global__ void count_k(const int* __restrict__ dst, int E) {
    int i = blockIdx.x * blockDim.x + threadIdx.x;
    if (i < E) atomicAdd(&g_cnt[dst[i]], 1);
}

__global__ void dinv_k(int N) {
    int i = blockIdx.x * blockDim.x + threadIdx.x;
    if (i < N) g_dinv[i] = rsqrtf((float)g_cnt[i] + 1.0f);
}

__global__ void scan1_k(int N) {
    __shared__ int sh[1024];
    int i = blockIdx.x * 1024 + threadIdx.x;
    int v = (i < N) ? g_cnt[i] : 0;
    sh[threadIdx.x] = v;
    __syncthreads();
    for (int d = 1; d < 1024; d <<= 1) {
        int t = (threadIdx.x >= d) ? sh[threadIdx.x - d] : 0;
        __syncthreads();
        sh[threadIdx.x] += t;
        __syncthreads();
    }
    if (i < N) g_off[i] = sh[threadIdx.x] - v;  // exclusive
    if (threadIdx.x == 1023) g_bsum[blockIdx.x] = sh[1023];
}

__global__ void scan2_k(int nb) {
    __shared__ int sh[128];
    int t = threadIdx.x;
    int v = (t < nb) ? g_bsum[t] : 0;
    sh[t] = v;
    __syncthreads();
    for (int d = 1; d < 128; d <<= 1) {
        int x = (t >= d) ? sh[t - d] : 0;
        __syncthreads();
        sh[t] += x;
        __syncthreads();
    }
    if (t < nb) g_bsum[t] = sh[t] - v;  // exclusive over block sums
}

__global__ void scan3_k(int N) {
    int i = blockIdx.x * 1024 + threadIdx.x;
    if (i < N) {
        int o = g_off[i] + g_bsum[blockIdx.x];
        g_off[i]    = o;
        g_cursor[i] = o;
    }
}

__global__ void scatter_k(const int* __restrict__ src, const int* __restrict__ dst, int E) {
    int i = blockIdx.x * blockDim.x + threadIdx.x;
    if (i < E) {
        int d = dst[i];
        int p = atomicAdd(&g_cursor[d], 1);
        int s = src[i];
        g_srt[p] = s;
        g_wsr[p] = g_dinv[s];
    }
}

// ---------------- BN fold: y = t*scale + shift, t = agg + bias --------------
__global__ void bnprep_k(const float* __restrict__ g, const float* __restrict__ be,
                         const float* __restrict__ m, const float* __restrict__ v,
                         const float* __restrict__ b, float* __restrict__ sc,
                         float* __restrict__ sh, int F) {
    int i = threadIdx.x;
    if (i < F) {
        float s = g[i] * rsqrtf(v[i] + 1e-5f);
        sc[i] = s;
        sh[i] = (b[i] - m[i]) * s + be[i];
    }
}

// ---------------- dense GEMM: Y[N,FO] = X[N,K] @ W[K,FO]  -------------------
// One thread per row, FOT accumulators in registers, W tile in shared.
// EPI==1 fuses (acc*scale + shift, relu).
template <int K, int FO, int FOT, int EPI>
__global__ void __launch_bounds__(256) gemm_k(
    const float* __restrict__ X, const float* __restrict__ W,
    const float* __restrict__ sc, const float* __restrict__ sh,
    float* __restrict__ Y, int N)
{
    __shared__ float Wsh[K * FOT];
    const int colbase = blockIdx.y * FOT;
    for (int idx = threadIdx.x; idx < K * FOT; idx += blockDim.x)
        Wsh[idx] = W[(idx / FOT) * FO + colbase + (idx % FOT)];
    __syncthreads();

    int row = blockIdx.x * blockDim.x + threadIdx.x;
    if (row >= N) return;

    float acc[FOT];
#pragma unroll
    for (int j = 0; j < FOT; j++) acc[j] = 0.f;

    const float4* X4 = reinterpret_cast<const float4*>(X) + (size_t)row * (K / 4);
#pragma unroll 2
    for (int k4 = 0; k4 < K / 4; k4++) {
        float4 xq = X4[k4];
        const float* wr = Wsh + k4 * 4 * FOT;
#pragma unroll
        for (int j4 = 0; j4 < FOT / 4; j4++) {
            float4 w0 = *(const float4*)(wr + 0 * FOT + j4 * 4);
            float4 w1 = *(const float4*)(wr + 1 * FOT + j4 * 4);
            float4 w2 = *(const float4*)(wr + 2 * FOT + j4 * 4);
            float4 w3 = *(const float4*)(wr + 3 * FOT + j4 * 4);
            acc[j4 * 4 + 0] += xq.x * w0.x + xq.y * w1.x + xq.z * w2.x + xq.w * w3.x;
            acc[j4 * 4 + 1] += xq.x * w0.y + xq.y * w1.y + xq.z * w2.y + xq.w * w3.y;
            acc[j4 * 4 + 2] += xq.x * w0.z + xq.y * w1.z + xq.z * w2.z + xq.w * w3.z;
            acc[j4 * 4 + 3] += xq.x * w0.w + xq.y * w1.w + xq.z * w2.w + xq.w * w3.w;
        }
    }

    float4* Yr = reinterpret_cast<float4*>(Y + (size_t)row * FO + colbase);
#pragma unroll
    for (int j4 = 0; j4 < FOT / 4; j4++) {
        float4 r;
        r.x = acc[j4 * 4 + 0];
        r.y = acc[j4 * 4 + 1];
        r.z = acc[j4 * 4 + 2];
        r.w = acc[j4 * 4 + 3];
        if (EPI == 1) {
            int f = colbase + j4 * 4;
            r.x = fmaxf(r.x * sc[f + 0] + sh[f + 0], 0.f);
            r.y = fmaxf(r.y * sc[f + 1] + sh[f + 1], 0.f);
            r.z = fmaxf(r.z * sc[f + 2] + sh[f + 2], 0.f);
            r.w = fmaxf(r.w * sc[f + 3] + sh[f + 3], 0.f);
        }
        Yr[j4] = r;
    }
}

// ---------------- CSR aggregation: OUT[d] = dinv[d]*Sum dinv[s]*XW[s] + dinv[d]^2*XW[d]
// MODE 0: none (pre-GEMM aggregate). MODE 1: fused bias+BN+relu (p0=scale,p1=shift).
// MODE 2: +bias only (p0=bias).
// One warp per node (F>=32); two nodes per warp for F==16.
template <int F, int MODE>
__global__ void agg_k(const float* __restrict__ XW,
                      const float* __restrict__ p0, const float* __restrict__ p1,
                      float* __restrict__ OUT, int N)
{
    int gwarp = (blockIdx.x * blockDim.x + threadIdx.x) >> 5;
    int lane  = threadIdx.x & 31;
    int d, fl;
    if (F == 16) { d = gwarp * 2 + (lane >> 4); fl = lane & 15; }
    else         { d = gwarp;                   fl = lane; }
    if (d >= N) return;

    const int base = g_off[d];
    const int n    = g_cnt[d];
    const float di = g_dinv[d];

    if (F == 64) {
        const float2* X2 = reinterpret_cast<const float2*>(XW);
        float2 acc = make_float2(0.f, 0.f);
        int i = 0;
        for (; i + 4 <= n; i += 4) {
            int   s0 = g_srt[base + i + 0], s1 = g_srt[base + i + 1];
            int   s2 = g_srt[base + i + 2], s3 = g_srt[base + i + 3];
            float w0 = g_wsr[base + i + 0], w1 = g_wsr[base + i + 1];
            float w2 = g_wsr[base + i + 2], w3 = g_wsr[base + i + 3];
            float2 v0 = X2[(size_t)s0 * 32 + fl];
            float2 v1 = X2[(size_t)s1 * 32 + fl];
            float2 v2 = X2[(size_t)s2 * 32 + fl];
            float2 v3 = X2[(size_t)s3 * 32 + fl];
            acc.x += v0.x * w0; acc.y += v0.y * w0;
            acc.x += v1.x * w1; acc.y += v1.y * w1;
            acc.x += v2.x * w2; acc.y += v2.y * w2;
            acc.x += v3.x * w3; acc.y += v3.y * w3;
        }
        for (; i < n; i++) {
            int s = g_srt[base + i];
            float w = g_wsr[base + i];
            float2 v = X2[(size_t)s * 32 + fl];
            acc.x += v.x * w; acc.y += v.y * w;
        }
        float2 self = X2[(size_t)d * 32 + fl];
        float rx = di * acc.x + di * di * self.x;
        float ry = di * acc.y + di * di * self.y;
        int f = fl * 2;
        if (MODE == 1) {
            rx = fmaxf(rx * p0[f] + p1[f], 0.f);
            ry = fmaxf(ry * p0[f + 1] + p1[f + 1], 0.f);
        } else if (MODE == 2) {
            rx += p0[f]; ry += p0[f + 1];
        }
        reinterpret_cast<float2*>(OUT)[(size_t)d * 32 + fl] = make_float2(rx, ry);
    } else {
        float acc = 0.f;
        int i = 0;
        for (; i + 4 <= n; i += 4) {
            int   s0 = g_srt[base + i + 0], s1 = g_srt[base + i + 1];
            int   s2 = g_srt[base + i + 2], s3 = g_srt[base + i + 3];
            float w0 = g_wsr[base + i + 0], w1 = g_wsr[base + i + 1];
            float w2 = g_wsr[base + i + 2], w3 = g_wsr[base + i + 3];
            float v0 = XW[(size_t)s0 * F + fl];
            float v1 = XW[(size_t)s1 * F + fl];
            float v2 = XW[(size_t)s2 * F + fl];
            float v3 = XW[(size_t)s3 * F + fl];
            acc += v0 * w0 + v1 * w1 + v2 * w2 + v3 * w3;
        }
        for (; i < n; i++)
            acc += XW[(size_t)g_srt[base + i] * F + fl] * g_wsr[base + i];
        float self = XW[(size_t)d * F + fl];
        float r = di * acc + di * di * self;
        if (MODE == 1)      r = fmaxf(r * p0[fl] + p1[fl], 0.f);
        else if (MODE == 2) r += p0[fl];
        OUT[(size_t)d * F + fl] = r;
    }
}

// ---------------- launch ----------------------------------------------------
extern "C" void kernel_launch(void* const* d_in, const int* in_sizes, int n_in,
                              void* d_out, int out_size)
{
    const float* x  = (const float*)d_in[0];
    const int*   ei = (const int*)d_in[1];
    const float* w1 = (const float*)d_in[2];
    const float* b1 = (const float*)d_in[3];
    const float* w2 = (const float*)d_in[4];
    const float* b2 = (const float*)d_in[5];
    const float* w3 = (const float*)d_in[6];
    const float* b3 = (const float*)d_in[7];
    const float* w4 = (const float*)d_in[8];
    const float* b4 = (const float*)d_in[9];
    const float* w5 = (const float*)d_in[10];
    const float* b5 = (const float*)d_in[11];
    const float* g1 = (const float*)d_in[12]; const float* be1 = (const float*)d_in[13];
    const float* m1 = (const float*)d_in[14]; const float* v1  = (const float*)d_in[15];
    const float* g2 = (const float*)d_in[16]; const float* be2 = (const float*)d_in[17];
    const float* m2 = (const float*)d_in[18]; const float* v2  = (const float*)d_in[19];
    const float* g3 = (const float*)d_in[20]; const float* be3 = (const float*)d_in[21];
    const float* m3 = (const float*)d_in[22]; const float* v3  = (const float*)d_in[23];
    const float* g4 = (const float*)d_in[24]; const float* be4 = (const float*)d_in[25];
    const float* m4 = (const float*)d_in[26]; const float* v4  = (const float*)d_in[27];

    const int N = in_sizes[0] / 128;
    const int E = in_sizes[1] / 2;
    const int* e_src = ei;
    const int* e_dst = ei + E;

    float *bufA, *bufB, *scb, *shb;
    cudaGetSymbolAddress((void**)&bufA, g_bufA);
    cudaGetSymbolAddress((void**)&bufB, g_bufB);
    cudaGetSymbolAddress((void**)&scb, g_scale);
    cudaGetSymbolAddress((void**)&shb, g_shift);

    const int nb256 = (N + 255) / 256;
    const int eb256 = (E + 255) / 256;
    const int NB    = (N + 1023) / 1024;

    // CSR + degree preprocessing
    zero_cnt_k<<<nb256, 256>>>(N);
    count_k<<<eb256, 256>>>(e_dst, E);
    dinv_k<<<nb256, 256>>>(N);
    scan1_k<<<NB, 1024>>>(N);
    scan2_k<<<1, 128>>>(NB);
    scan3_k<<<NB, 1024>>>(N);
    scatter_k<<<eb256, 256>>>(e_src, e_dst, E);

    // BN affine folds (layers 1..4)
    bnprep_k<<<1, 128>>>(g1, be1, m1, v1, b1, scb + 0,   shb + 0,   64);
    bnprep_k<<<1, 128>>>(g2, be2, m2, v2, b2, scb + 128, shb + 128, 128);
    bnprep_k<<<1, 128>>>(g3, be3, m3, v3, b3, scb + 256, shb + 256, 64);
    bnprep_k<<<1, 128>>>(g4, be4, m4, v4, b4, scb + 384, shb + 384, 32);

    const int gb = (N + 255) / 256;           // gemm blocks (1 row/thread)
    const int ab = (N + 7) / 8;               // agg blocks (1 warp/node, 8 warps/blk)

    // L1 (128->64): GEMM first, aggregate 64 feats, fuse bias+BN+relu
    gemm_k<128, 64, 64, 0><<<gb, 256>>>(x, w1, nullptr, nullptr, bufA, N);
    agg_k<64, 1><<<ab, 256>>>(bufA, scb + 0, shb + 0, bufB, N);

    // L2 (64->128): aggregate first (64 feats), then GEMM with fused bias+BN+relu
    agg_k<64, 0><<<ab, 256>>>(bufB, nullptr, nullptr, bufA, N);
    gemm_k<64, 128, 64, 1><<<dim3(gb, 2), 256>>>(bufA, w2, scb + 128, shb + 128, bufB, N);

    // L3 (128->64): GEMM first
    gemm_k<128, 64, 64, 0><<<gb, 256>>>(bufB, w3, nullptr, nullptr, bufA, N);
    agg_k<64, 1><<<ab, 256>>>(bufA, scb + 256, shb + 256, bufB, N);

    // L4 (64->32): GEMM first
    gemm_k<64, 32, 32, 0><<<gb, 256>>>(bufB, w4, nullptr, nullptr, bufA, N);
    agg_k<32, 1><<<ab, 256>>>(bufA, scb + 384, shb + 384, bufB, N);

    // L5 (32->16): GEMM first, aggregate + bias only -> d_out
    gemm_k<32, 16, 16, 0><<<gb, 256>>>(bufB, w5, nullptr, nullptr, bufA, N);
    const int ab16 = (((N + 1) / 2) + 7) / 8;
    agg_k<16, 2><<<ab16, 256>>>(bufA, b5, nullptr, (float*)d_out, N);
}

// round 11
// speedup vs baseline: 1.0007x; 1.0007x over previous
#include <cuda_runtime.h>

// Problem constants (fixed by the dataset)
#define NMAX 100000
#define EMAX 1600000

// ---------------- device scratch (no runtime allocation allowed) ------------
__device__ float4 g_bufA[NMAX * 128 / 4];   // 51.2 MB ping
__device__ float4 g_bufB[NMAX * 128 / 4];   // 51.2 MB pong
__device__ float  g_dinv[NMAX];
__device__ int    g_cnt[NMAX];
__device__ int    g_off[NMAX];
__device__ int    g_cursor[NMAX];
__device__ int    g_srt[EMAX];              // edge src sorted by dst (CSR)
__device__ float  g_wsr[EMAX];              // dinv[src] per sorted edge
__device__ int    g_bsum[128];
__device__ float  g_scale[4 * 128];         // folded BN scale per layer
__device__ float  g_shift[4 * 128];         // folded BN shift per layer

// ---------------- CSR build ------------------------------------------------
__global__ void zero_cnt_k(int N) {
    int i = blockIdx.x * blockDim.x + threadIdx.x;
    if (i < N) g_cnt[i] = 0;
}

__global__ void count_k(const int* __restrict__ dst, int E) {
    int i = blockIdx.x * blockDim.x + threadIdx.x;
    if (i < E) atomicAdd(&g_cnt[dst[i]], 1);
}

__global__ void dinv_k(int N) {
    int i = blockIdx.x * blockDim.x + threadIdx.x;
    if (i < N) g_dinv[i] = rsqrtf((float)g_cnt[i] + 1.0f);
}

__global__ void scan1_k(int N) {
    __shared__ int sh[1024];
    int i = blockIdx.x * 1024 + threadIdx.x;
    int v = (i < N) ? g_cnt[i] : 0;
    sh[threadIdx.x] = v;
    __syncthreads();
    for (int d = 1; d < 1024; d <<= 1) {
        int t = (threadIdx.x >= d) ? sh[threadIdx.x - d] : 0;
        __syncthreads();
        sh[threadIdx.x] += t;
        __syncthreads();
    }
    if (i < N) g_off[i] = sh[threadIdx.x] - v;  // exclusive
    if (threadIdx.x == 1023) g_bsum[blockIdx.x] = sh[1023];
}

__global__ void scan2_k(int nb) {
    __shared__ int sh[128];
    int t = threadIdx.x;
    int v = (t < nb) ? g_bsum[t] : 0;
    sh[t] = v;
    __syncthreads();
    for (int d = 1; d < 128; d <<= 1) {
        int x = (t >= d) ? sh[t - d] : 0;
        __syncthreads();
        sh[t] += x;
        __syncthreads();
    }
    if (t < nb) g_bsum[t] = sh[t] - v;  // exclusive over block sums
}

__global__ void scan3_k(int N) {
    int i = blockIdx.x * 1024 + threadIdx.x;
    if (i < N) {
        int o = g_off[i] + g_bsum[blockIdx.x];
        g_off[i]    = o;
        g_cursor[i] = o;
    }
}

__global__ void scatter_k(const int* __restrict__ src, const int* __restrict__ dst, int E) {
    int i = blockIdx.x * blockDim.x + threadIdx.x;
    if (i < E) {
        int d = dst[i];
        int p = atomicAdd(&g_cursor[d], 1);
        int s = src[i];
        g_srt[p] = s;
        g_wsr[p] = g_dinv[s];
    }
}

// ---------------- BN fold: y = t*scale + shift, t = agg + bias --------------
__global__ void bnprep_k(const float* __restrict__ g, const float* __restrict__ be,
                         const float* __restrict__ m, const float* __restrict__ v,
                         const float* __restrict__ b, float* __restrict__ sc,
                         float* __restrict__ sh, int F) {
    int i = threadIdx.x;
    if (i < F) {
        float s = g[i] * rsqrtf(v[i] + 1e-5f);
        sc[i] = s;
        sh[i] = (b[i] - m[i]) * s + be[i];
    }
}

// ---------------- dense GEMM: Y[N,FO] = X[N,K] @ W[K,FO]  -------------------
// One thread per row, FOT accumulators in registers, W tile in shared.
// EPI==1 fuses (acc*scale + shift, relu).
template <int K, int FO, int FOT, int EPI>
__global__ void __launch_bounds__(256) gemm_k(
    const float* __restrict__ X, const float* __restrict__ W,
    const float* __restrict__ sc, const float* __restrict__ sh,
    float* __restrict__ Y, int N)
{
    __shared__ float Wsh[K * FOT];
    const int colbase = blockIdx.y * FOT;
    for (int idx = threadIdx.x; idx < K * FOT; idx += blockDim.x)
        Wsh[idx] = W[(idx / FOT) * FO + colbase + (idx % FOT)];
    __syncthreads();

    int row = blockIdx.x * blockDim.x + threadIdx.x;
    if (row >= N) return;

    float acc[FOT];
#pragma unroll
    for (int j = 0; j < FOT; j++) acc[j] = 0.f;

    const float4* X4 = reinterpret_cast<const float4*>(X) + (size_t)row * (K / 4);
#pragma unroll 2
    for (int k4 = 0; k4 < K / 4; k4++) {
        float4 xq = X4[k4];
        const float* wr = Wsh + k4 * 4 * FOT;
#pragma unroll
        for (int j4 = 0; j4 < FOT / 4; j4++) {
            float4 w0 = *(const float4*)(wr + 0 * FOT + j4 * 4);
            float4 w1 = *(const float4*)(wr + 1 * FOT + j4 * 4);
            float4 w2 = *(const float4*)(wr + 2 * FOT + j4 * 4);
            float4 w3 = *(const float4*)(wr + 3 * FOT + j4 * 4);
            acc[j4 * 4 + 0] += xq.x * w0.x + xq.y * w1.x + xq.z * w2.x + xq.w * w3.x;
            acc[j4 * 4 + 1] += xq.x * w0.y + xq.y * w1.y + xq.z * w2.y + xq.w * w3.y;
            acc[j4 * 4 + 2] += xq.x * w0.z + xq.y * w1.z + xq.z * w2.z + xq.w * w3.z;
            acc[j4 * 4 + 3] += xq.x * w0.w + xq.y * w1.w + xq.z * w2.w + xq.w * w3.w;
        }
    }

    float4* Yr = reinterpret_cast<float4*>(Y + (size_t)row * FO + colbase);
#pragma unroll
    for (int j4 = 0; j4 < FOT / 4; j4++) {
        float4 r;
        r.x = acc[j4 * 4 + 0];
        r.y = acc[j4 * 4 + 1];
        r.z = acc[j4 * 4 + 2];
        r.w = acc[j4 * 4 + 3];
        if (EPI == 1) {
            int f = colbase + j4 * 4;
            r.x = fmaxf(r.x * sc[f + 0] + sh[f + 0], 0.f);
            r.y = fmaxf(r.y * sc[f + 1] + sh[f + 1], 0.f);
            r.z = fmaxf(r.z * sc[f + 2] + sh[f + 2], 0.f);
            r.w = fmaxf(r.w * sc[f + 3] + sh[f + 3], 0.f);
        }
        Yr[j4] = r;
    }
}

// ---------------- CSR aggregation: OUT[d] = dinv[d]*Sum dinv[s]*XW[s] + dinv[d]^2*XW[d]
// MODE 0: none (pre-GEMM aggregate). MODE 1: fused bias+BN+relu (p0=scale,p1=shift).
// MODE 2: +bias only (p0=bias).
// One warp per node (F>=32); two nodes per warp for F==16.
template <int F, int MODE>
__global__ void agg_k(const float* __restrict__ XW,
                      const float* __restrict__ p0, const float* __restrict__ p1,
                      float* __restrict__ OUT, int N)
{
    int gwarp = (blockIdx.x * blockDim.x + threadIdx.x) >> 5;
    int lane  = threadIdx.x & 31;
    int d, fl;
    if (F == 16) { d = gwarp * 2 + (lane >> 4); fl = lane & 15; }
    else         { d = gwarp;                   fl = lane; }
    if (d >= N) return;

    const int base = g_off[d];
    const int n    = g_cnt[d];
    const float di = g_dinv[d];

    if (F == 64) {
        const float2* X2 = reinterpret_cast<const float2*>(XW);
        float2 acc = make_float2(0.f, 0.f);
        int i = 0;
        for (; i + 4 <= n; i += 4) {
            int   s0 = g_srt[base + i + 0], s1 = g_srt[base + i + 1];
            int   s2 = g_srt[base + i + 2], s3 = g_srt[base + i + 3];
            float w0 = g_wsr[base + i + 0], w1 = g_wsr[base + i + 1];
            float w2 = g_wsr[base + i + 2], w3 = g_wsr[base + i + 3];
            float2 v0 = X2[(size_t)s0 * 32 + fl];
            float2 v1 = X2[(size_t)s1 * 32 + fl];
            float2 v2 = X2[(size_t)s2 * 32 + fl];
            float2 v3 = X2[(size_t)s3 * 32 + fl];
            acc.x += v0.x * w0; acc.y += v0.y * w0;
            acc.x += v1.x * w1; acc.y += v1.y * w1;
            acc.x += v2.x * w2; acc.y += v2.y * w2;
            acc.x += v3.x * w3; acc.y += v3.y * w3;
        }
        for (; i < n; i++) {
            int s = g_srt[base + i];
            float w = g_wsr[base + i];
            float2 v = X2[(size_t)s * 32 + fl];
            acc.x += v.x * w; acc.y += v.y * w;
        }
        float2 self = X2[(size_t)d * 32 + fl];
        float rx = di * acc.x + di * di * self.x;
        float ry = di * acc.y + di * di * self.y;
        int f = fl * 2;
        if (MODE == 1) {
            rx = fmaxf(rx * p0[f] + p1[f], 0.f);
            ry = fmaxf(ry * p0[f + 1] + p1[f + 1], 0.f);
        } else if (MODE == 2) {
            rx += p0[f]; ry += p0[f + 1];
        }
        reinterpret_cast<float2*>(OUT)[(size_t)d * 32 + fl] = make_float2(rx, ry);
    } else {
        float acc = 0.f;
        int i = 0;
        for (; i + 4 <= n; i += 4) {
            int   s0 = g_srt[base + i + 0], s1 = g_srt[base + i + 1];
            int   s2 = g_srt[base + i + 2], s3 = g_srt[base + i + 3];
            float w0 = g_wsr[base + i + 0], w1 = g_wsr[base + i + 1];
            float w2 = g_wsr[base + i + 2], w3 = g_wsr[base + i + 3];
            float v0 = XW[(size_t)s0 * F + fl];
            float v1 = XW[(size_t)s1 * F + fl];
            float v2 = XW[(size_t)s2 * F + fl];
            float v3 = XW[(size_t)s3 * F + fl];
            acc += v0 * w0 + v1 * w1 + v2 * w2 + v3 * w3;
        }
        for (; i < n; i++)
            acc += XW[(size_t)g_srt[base + i] * F + fl] * g_wsr[base + i];
        float self = XW[(size_t)d * F + fl];
        float r = di * acc + di * di * self;
        if (MODE == 1)      r = fmaxf(r * p0[fl] + p1[fl], 0.f);
        else if (MODE == 2) r += p0[fl];
        OUT[(size_t)d * F + fl] = r;
    }
}

// ---------------- launch ----------------------------------------------------
extern "C" void kernel_launch(void* const* d_in, const int* in_sizes, int n_in,
                              void* d_out, int out_size)
{
    const float* x  = (const float*)d_in[0];
    const int*   ei = (const int*)d_in[1];
    const float* w1 = (const float*)d_in[2];
    const float* b1 = (const float*)d_in[3];
    const float* w2 = (const float*)d_in[4];
    const float* b2 = (const float*)d_in[5];
    const float* w3 = (const float*)d_in[6];
    const float* b3 = (const float*)d_in[7];
    const float* w4 = (const float*)d_in[8];
    const float* b4 = (const float*)d_in[9];
    const float* w5 = (const float*)d_in[10];
    const float* b5 = (const float*)d_in[11];
    const float* g1 = (const float*)d_in[12]; const float* be1 = (const float*)d_in[13];
    const float* m1 = (const float*)d_in[14]; const float* v1  = (const float*)d_in[15];
    const float* g2 = (const float*)d_in[16]; const float* be2 = (const float*)d_in[17];
    const float* m2 = (const float*)d_in[18]; const float* v2  = (const float*)d_in[19];
    const float* g3 = (const float*)d_in[20]; const float* be3 = (const float*)d_in[21];
    const float* m3 = (const float*)d_in[22]; const float* v3  = (const float*)d_in[23];
    const float* g4 = (const float*)d_in[24]; const float* be4 = (const float*)d_in[25];
    const float* m4 = (const float*)d_in[26]; const float* v4  = (const float*)d_in[27];

    const int N = in_sizes[0] / 128;
    const int E = in_sizes[1] / 2;
    const int* e_src = ei;
    const int* e_dst = ei + E;

    float *bufA, *bufB, *scb, *shb;
    cudaGetSymbolAddress((void**)&bufA, g_bufA);
    cudaGetSymbolAddress((void**)&bufB, g_bufB);
    cudaGetSymbolAddress((void**)&scb, g_scale);
    cudaGetSymbolAddress((void**)&shb, g_shift);

    const int nb256 = (N + 255) / 256;
    const int eb256 = (E + 255) / 256;
    const int NB    = (N + 1023) / 1024;

    // CSR + degree preprocessing
    zero_cnt_k<<<nb256, 256>>>(N);
    count_k<<<eb256, 256>>>(e_dst, E);
    dinv_k<<<nb256, 256>>>(N);
    scan1_k<<<NB, 1024>>>(N);
    scan2_k<<<1, 128>>>(NB);
    scan3_k<<<NB, 1024>>>(N);
    scatter_k<<<eb256, 256>>>(e_src, e_dst, E);

    // BN affine folds (layers 1..4)
    bnprep_k<<<1, 128>>>(g1, be1, m1, v1, b1, scb + 0,   shb + 0,   64);
    bnprep_k<<<1, 128>>>(g2, be2, m2, v2, b2, scb + 128, shb + 128, 128);
    bnprep_k<<<1, 128>>>(g3, be3, m3, v3, b3, scb + 256, shb + 256, 64);
    bnprep_k<<<1, 128>>>(g4, be4, m4, v4, b4, scb + 384, shb + 384, 32);

    const int gb = (N + 255) / 256;           // gemm blocks (1 row/thread)
    const int ab = (N + 7) / 8;               // agg blocks (1 warp/node, 8 warps/blk)

    // L1 (128->64): GEMM first, aggregate 64 feats, fuse bias+BN+relu
    gemm_k<128, 64, 64, 0><<<gb, 256>>>(x, w1, nullptr, nullptr, bufA, N);
    agg_k<64, 1><<<ab, 256>>>(bufA, scb + 0, shb + 0, bufB, N);

    // L2 (64->128): aggregate first (64 feats), then GEMM with fused bias+BN+relu
    agg_k<64, 0><<<ab, 256>>>(bufB, nullptr, nullptr, bufA, N);
    gemm_k<64, 128, 64, 1><<<dim3(gb, 2), 256>>>(bufA, w2, scb + 128, shb + 128, bufB, N);

    // L3 (128->64): GEMM first
    gemm_k<128, 64, 64, 0><<<gb, 256>>>(bufB, w3, nullptr, nullptr, bufA, N);
    agg_k<64, 1><<<ab, 256>>>(bufA, scb + 256, shb + 256, bufB, N);

    // L4 (64->32): GEMM first
    gemm_k<64, 32, 32, 0><<<gb, 256>>>(bufB, w4, nullptr, nullptr, bufA, N);
    agg_k<32, 1><<<ab, 256>>>(bufA, scb + 384, shb + 384, bufB, N);

    // L5 (32->16): GEMM first, aggregate + bias only -> d_out
    gemm_k<32, 16, 16, 0><<<gb, 256>>>(bufB, w5, nullptr, nullptr, bufA, N);
    const int ab16 = (((N + 1) / 2) + 7) / 8;
    agg_k<16, 2><<<ab16, 256>>>(bufA, b5, nullptr, (float*)d_out, N);
}